// round 3
// baseline (speedup 1.0000x reference)
#include <cuda_runtime.h>
#include <math.h>

#define B 128
#define C 1024
#define DIN 1024
#define TWO_D 2048
#define NUM_CLASSES 10
#define ALPHA 1e-3f
#define GAMMA 1e-2f

#define BM 32
#define BN 32
#define BK 64
#define PAD 2
#define KSPLIT 2

// Scratch (static device globals are allowed; no dynamic allocation)
__device__ float g_pmin[B];
__device__ float g_pmax[B];
__device__ float g_mn;
__device__ float g_scale;
__device__ float g_coded[B * TWO_D];
__device__ float g_den[C];
__device__ float g_part[KSPLIT][B][C];

// ---------------------------------------------------------------------------
// K1: per-batch-row min/max partials of x
// ---------------------------------------------------------------------------
__global__ void k_minmax_partial(const float* __restrict__ x) {
    int b = blockIdx.x;
    int t = threadIdx.x;
    const float* row = x + b * DIN;
    float mn = 1e30f, mx = -1e30f;
    for (int k = t; k < DIN; k += 128) {
        float v = row[k];
        mn = fminf(mn, v);
        mx = fmaxf(mx, v);
    }
    #pragma unroll
    for (int o = 16; o > 0; o >>= 1) {
        mn = fminf(mn, __shfl_xor_sync(0xffffffffu, mn, o));
        mx = fmaxf(mx, __shfl_xor_sync(0xffffffffu, mx, o));
    }
    __shared__ float smn[4], smx[4];
    if ((t & 31) == 0) { smn[t >> 5] = mn; smx[t >> 5] = mx; }
    __syncthreads();
    if (t == 0) {
        mn = smn[0]; mx = smx[0];
        #pragma unroll
        for (int w = 1; w < 4; w++) { mn = fminf(mn, smn[w]); mx = fmaxf(mx, smx[w]); }
        g_pmin[b] = mn;
        g_pmax[b] = mx;
    }
}

// ---------------------------------------------------------------------------
// K2: final min/max reduce -> g_mn, g_scale
// ---------------------------------------------------------------------------
__global__ void k_minmax_final() {
    int t = threadIdx.x;  // 128 threads
    float mn = g_pmin[t];
    float mx = g_pmax[t];
    #pragma unroll
    for (int o = 16; o > 0; o >>= 1) {
        mn = fminf(mn, __shfl_xor_sync(0xffffffffu, mn, o));
        mx = fmaxf(mx, __shfl_xor_sync(0xffffffffu, mx, o));
    }
    __shared__ float smn[4], smx[4];
    if ((t & 31) == 0) { smn[t >> 5] = mn; smx[t >> 5] = mx; }
    __syncthreads();
    if (t == 0) {
        mn = smn[0]; mx = smx[0];
        #pragma unroll
        for (int w = 1; w < 4; w++) { mn = fminf(mn, smn[w]); mx = fmaxf(mx, smx[w]); }
        g_mn = mn;
        g_scale = 1.0f / (mx - mn + 1e-10f);
    }
}

// ---------------------------------------------------------------------------
// K3: blocks [0,C): den[c] = alpha + rowsum(T[c]) + gamma*counts[c]
//     blocks [C,C+B): complement-coded input rows
// ---------------------------------------------------------------------------
__global__ void k_prep(const float* __restrict__ x,
                       const float* __restrict__ T,
                       const int* __restrict__ counts) {
    int blk = blockIdx.x;
    int t = threadIdx.x;  // 256 threads
    if (blk < C) {
        const float4* row = (const float4*)(T + (size_t)blk * TWO_D);
        float s = 0.0f;
        #pragma unroll
        for (int i = 0; i < 2; i++) {
            float4 v = row[t + i * 256];
            s += (v.x + v.y) + (v.z + v.w);
        }
        #pragma unroll
        for (int o = 16; o > 0; o >>= 1)
            s += __shfl_xor_sync(0xffffffffu, s, o);
        __shared__ float ss[8];
        if ((t & 31) == 0) ss[t >> 5] = s;
        __syncthreads();
        if (t == 0) {
            #pragma unroll
            for (int w = 1; w < 8; w++) s += ss[w];
            g_den[blk] = ALPHA + s + GAMMA * (float)counts[blk];
        }
    } else {
        int b = blk - C;
        float mn = g_mn;
        float sc = g_scale;
        const float* xr = x + (size_t)b * DIN;
        float* cr = g_coded + (size_t)b * TWO_D;
        #pragma unroll
        for (int i = 0; i < 4; i++) {
            int k = t + i * 256;
            float xn = (xr[k] - mn) * sc;
            cr[k] = xn;
            cr[DIN + k] = 1.0f - xn;
        }
    }
}

// ---------------------------------------------------------------------------
// K4: min-sum "GEMM". Tile BMxBN over a K-slice of 1024, partials to g_part.
// grid = (C/BN, B/BM, KSPLIT), 256 threads (16x16), TM=TN=2.
// ---------------------------------------------------------------------------
__global__ void __launch_bounds__(256) k_choice(const float* __restrict__ T) {
    __shared__ float sA[BK][BM + PAD];
    __shared__ float sB[BK][BN + PAD];

    int tid = threadIdx.x;
    int tx = tid & 15;
    int ty = tid >> 4;
    int bn = blockIdx.x;
    int bm = blockIdx.y;
    int ks = blockIdx.z;
    int mbase = bm * BM;
    int nbase = bn * BN;
    int k0base = ks * (TWO_D / KSPLIT);

    float acc00 = 0.f, acc01 = 0.f, acc10 = 0.f, acc11 = 0.f;

    // tile-load mapping: u in [0,512): m = u>>4 (0..31), kv = u&15 (float4 idx)
    int m0 = tid >> 4,          kv0 = tid & 15;
    int m1 = (tid + 256) >> 4,  kv1 = (tid + 256) & 15;

    for (int kt = 0; kt < TWO_D / KSPLIT; kt += BK) {
        int k0 = k0base + kt;
        {
            float4 v = *(const float4*)&g_coded[(size_t)(mbase + m0) * TWO_D + k0 + kv0 * 4];
            sA[kv0 * 4 + 0][m0] = v.x; sA[kv0 * 4 + 1][m0] = v.y;
            sA[kv0 * 4 + 2][m0] = v.z; sA[kv0 * 4 + 3][m0] = v.w;
            v = *(const float4*)&g_coded[(size_t)(mbase + m1) * TWO_D + k0 + kv1 * 4];
            sA[kv1 * 4 + 0][m1] = v.x; sA[kv1 * 4 + 1][m1] = v.y;
            sA[kv1 * 4 + 2][m1] = v.z; sA[kv1 * 4 + 3][m1] = v.w;

            v = *(const float4*)&T[(size_t)(nbase + m0) * TWO_D + k0 + kv0 * 4];
            sB[kv0 * 4 + 0][m0] = v.x; sB[kv0 * 4 + 1][m0] = v.y;
            sB[kv0 * 4 + 2][m0] = v.z; sB[kv0 * 4 + 3][m0] = v.w;
            v = *(const float4*)&T[(size_t)(nbase + m1) * TWO_D + k0 + kv1 * 4];
            sB[kv1 * 4 + 0][m1] = v.x; sB[kv1 * 4 + 1][m1] = v.y;
            sB[kv1 * 4 + 2][m1] = v.z; sB[kv1 * 4 + 3][m1] = v.w;
        }
        __syncthreads();
        #pragma unroll 16
        for (int k = 0; k < BK; k++) {
            float2 a  = *(const float2*)&sA[k][ty * 2];
            float2 bb = *(const float2*)&sB[k][tx * 2];
            acc00 += fminf(a.x, bb.x);
            acc01 += fminf(a.x, bb.y);
            acc10 += fminf(a.y, bb.x);
            acc11 += fminf(a.y, bb.y);
        }
        __syncthreads();
    }

    int b0 = mbase + ty * 2;
    int c0 = nbase + tx * 2;
    g_part[ks][b0][c0]         = acc00;
    g_part[ks][b0][c0 + 1]     = acc01;
    g_part[ks][b0 + 1][c0]     = acc10;
    g_part[ks][b0 + 1][c0 + 1] = acc11;
}

// ---------------------------------------------------------------------------
// K5: per batch row: combine K-slices, divide by den, masked argmax (first-
// index tie rule), per-label choice sums, write one_hot(pred) * label_sums.
// committed is int32 (bool inputs are materialized as int32 by the harness).
// ---------------------------------------------------------------------------
__global__ void k_epilogue(const int* __restrict__ committed,
                           const int* __restrict__ labels,
                           float* __restrict__ out) {
    int b = blockIdx.x;
    int t = threadIdx.x;  // 256 threads
    __shared__ float bins[NUM_CLASSES];
    __shared__ float sVal[256];
    __shared__ int sIdx[256];

    if (t < NUM_CLASSES) bins[t] = 0.0f;
    __syncthreads();

    float best = -INFINITY;
    int bestIdx = 0;
    #pragma unroll
    for (int i = 0; i < 4; i++) {
        int c = t + i * 256;
        float num = g_part[0][b][c] + g_part[1][b][c];
        float v = num / g_den[c];
        bool com = (committed[c] != 0);
        float mv = com ? v : -INFINITY;
        if (mv > best) { best = mv; bestIdx = c; }  // ascending c -> first-index on tie
        if (com) atomicAdd(&bins[labels[c]], v);
    }
    sVal[t] = best;
    sIdx[t] = bestIdx;
    __syncthreads();
    for (int s = 128; s > 0; s >>= 1) {
        if (t < s) {
            float ov = sVal[t + s];
            int oi = sIdx[t + s];
            if (ov > sVal[t] || (ov == sVal[t] && oi < sIdx[t])) {
                sVal[t] = ov; sIdx[t] = oi;
            }
        }
        __syncthreads();
    }
    if (t < NUM_CLASSES) {
        int pl = labels[sIdx[0]];
        out[b * NUM_CLASSES + t] = (t == pl) ? bins[t] : 0.0f;
    }
}

// ---------------------------------------------------------------------------
extern "C" void kernel_launch(void* const* d_in, const int* in_sizes, int n_in,
                              void* d_out, int out_size) {
    const float* x = (const float*)d_in[0];
    const float* T = (const float*)d_in[1];
    const int* committed = (const int*)d_in[2];
    const int* labels = (const int*)d_in[3];
    const int* counts = (const int*)d_in[4];
    float* out = (float*)d_out;

    k_minmax_partial<<<B, 128>>>(x);
    k_minmax_final<<<1, 128>>>();
    k_prep<<<C + B, 256>>>(x, T, counts);
    dim3 g4(C / BN, B / BM, KSPLIT);
    k_choice<<<g4, 256>>>(T);
    k_epilogue<<<B, 256>>>(committed, labels, out);
}

// round 4
// speedup vs baseline: 1.2704x; 1.2704x over previous
#include <cuda_runtime.h>
#include <math.h>

#define B 128
#define C 1024
#define DIN 1024
#define TWO_D 2048
#define NUM_CLASSES 10
#define ALPHA 1e-3f
#define GAMMA 1e-2f

#define BM 64
#define BN 64
#define BK 32
#define PAD 4
#define KSPLIT 8
#define KSLICE (TWO_D / KSPLIT)   // 256

// Scratch (static device globals; no dynamic allocation)
__device__ float g_pmin[B];
__device__ float g_pmax[B];
__device__ float g_coded[B * TWO_D];
__device__ float g_den[C];
__device__ float g_part[KSPLIT][B][C];

// ---------------------------------------------------------------------------
// K1: per-batch-row min/max partials of x
// ---------------------------------------------------------------------------
__global__ void k_minmax_partial(const float* __restrict__ x) {
    int b = blockIdx.x;
    int t = threadIdx.x;  // 128
    const float* row = x + b * DIN;
    float mn = 1e30f, mx = -1e30f;
    #pragma unroll
    for (int i = 0; i < 2; i++) {
        float4 v = ((const float4*)row)[t + i * 128];
        mn = fminf(mn, fminf(fminf(v.x, v.y), fminf(v.z, v.w)));
        mx = fmaxf(mx, fmaxf(fmaxf(v.x, v.y), fmaxf(v.z, v.w)));
    }
    #pragma unroll
    for (int o = 16; o > 0; o >>= 1) {
        mn = fminf(mn, __shfl_xor_sync(0xffffffffu, mn, o));
        mx = fmaxf(mx, __shfl_xor_sync(0xffffffffu, mx, o));
    }
    __shared__ float smn[4], smx[4];
    if ((t & 31) == 0) { smn[t >> 5] = mn; smx[t >> 5] = mx; }
    __syncthreads();
    if (t == 0) {
        mn = smn[0]; mx = smx[0];
        #pragma unroll
        for (int w = 1; w < 4; w++) { mn = fminf(mn, smn[w]); mx = fmaxf(mx, smx[w]); }
        g_pmin[b] = mn;
        g_pmax[b] = mx;
    }
}

// ---------------------------------------------------------------------------
// K2: blocks [0,C): den[c] = alpha + rowsum(T[c]) + gamma*counts[c]
//     blocks [C,C+B): final minmax reduce (local) + complement-coded rows
// ---------------------------------------------------------------------------
__global__ void k_prep(const float* __restrict__ x,
                       const float* __restrict__ T,
                       const int* __restrict__ counts) {
    int blk = blockIdx.x;
    int t = threadIdx.x;  // 256
    if (blk < C) {
        const float4* row = (const float4*)(T + (size_t)blk * TWO_D);
        float s = 0.0f;
        #pragma unroll
        for (int i = 0; i < 2; i++) {
            float4 v = row[t + i * 256];
            s += (v.x + v.y) + (v.z + v.w);
        }
        #pragma unroll
        for (int o = 16; o > 0; o >>= 1)
            s += __shfl_xor_sync(0xffffffffu, s, o);
        __shared__ float ss[8];
        if ((t & 31) == 0) ss[t >> 5] = s;
        __syncthreads();
        if (t == 0) {
            #pragma unroll
            for (int w = 1; w < 8; w++) s += ss[w];
            g_den[blk] = ALPHA + s + GAMMA * (float)counts[blk];
        }
    } else {
        int b = blk - C;
        // reduce the 128 per-row partials -> global min / scale
        __shared__ float smn[4], smx[4];
        float mn = 1e30f, mx = -1e30f;
        if (t < 128) {
            mn = g_pmin[t];
            mx = g_pmax[t];
            #pragma unroll
            for (int o = 16; o > 0; o >>= 1) {
                mn = fminf(mn, __shfl_xor_sync(0xffffffffu, mn, o));
                mx = fmaxf(mx, __shfl_xor_sync(0xffffffffu, mx, o));
            }
            if ((t & 31) == 0) { smn[t >> 5] = mn; smx[t >> 5] = mx; }
        }
        __syncthreads();
        mn = fminf(fminf(smn[0], smn[1]), fminf(smn[2], smn[3]));
        mx = fmaxf(fmaxf(smx[0], smx[1]), fmaxf(smx[2], smx[3]));
        float sc = 1.0f / (mx - mn + 1e-10f);

        const float* xr = x + (size_t)b * DIN;
        float* cr = g_coded + (size_t)b * TWO_D;
        #pragma unroll
        for (int i = 0; i < 4; i++) {
            int k = t + i * 256;
            float xn = (xr[k] - mn) * sc;
            cr[k] = xn;
            cr[DIN + k] = 1.0f - xn;
        }
    }
}

// ---------------------------------------------------------------------------
// K3: min-sum "GEMM". BM=BN=64, BK=32, 256 threads (16x16), TM=TN=4.
// grid = (C/BN, B/BM, KSPLIT). Partials to g_part[ks].
// ---------------------------------------------------------------------------
__global__ void __launch_bounds__(256) k_choice(const float* __restrict__ T) {
    __shared__ float sA[BK][BM + PAD];   // [k][m], row stride 68*4=272B (16B-mult)
    __shared__ float sB[BK][BN + PAD];   // [k][n]

    int tid = threadIdx.x;
    int tx = tid & 15;       // n-group
    int ty = tid >> 4;       // m-group
    int mbase = blockIdx.y * BM;
    int nbase = blockIdx.x * BN;
    int ks = blockIdx.z;
    int k0base = ks * KSLICE;

    float acc[4][4];
    #pragma unroll
    for (int i = 0; i < 4; i++)
        #pragma unroll
        for (int j = 0; j < 4; j++) acc[i][j] = 0.0f;

    int lrow = tid >> 3;     // 0..31
    int lkv = tid & 7;       // float4 index within BK

    for (int kt = 0; kt < KSLICE; kt += BK) {
        int k0 = k0base + kt;
        #pragma unroll
        for (int i = 0; i < 2; i++) {
            int r = lrow + i * 32;
            float4 v = *(const float4*)&g_coded[(size_t)(mbase + r) * TWO_D + k0 + lkv * 4];
            sA[lkv * 4 + 0][r] = v.x; sA[lkv * 4 + 1][r] = v.y;
            sA[lkv * 4 + 2][r] = v.z; sA[lkv * 4 + 3][r] = v.w;
            float4 w = *(const float4*)&T[(size_t)(nbase + r) * TWO_D + k0 + lkv * 4];
            sB[lkv * 4 + 0][r] = w.x; sB[lkv * 4 + 1][r] = w.y;
            sB[lkv * 4 + 2][r] = w.z; sB[lkv * 4 + 3][r] = w.w;
        }
        __syncthreads();
        #pragma unroll
        for (int k = 0; k < BK; k++) {
            float4 a = *(const float4*)&sA[k][ty * 4];
            float4 bb = *(const float4*)&sB[k][tx * 4];
            float av[4] = {a.x, a.y, a.z, a.w};
            float bv[4] = {bb.x, bb.y, bb.z, bb.w};
            #pragma unroll
            for (int i = 0; i < 4; i++)
                #pragma unroll
                for (int j = 0; j < 4; j++)
                    acc[i][j] += fminf(av[i], bv[j]);
        }
        __syncthreads();
    }

    int b0 = mbase + ty * 4;
    int c0 = nbase + tx * 4;
    #pragma unroll
    for (int i = 0; i < 4; i++) {
        float4 v = make_float4(acc[i][0], acc[i][1], acc[i][2], acc[i][3]);
        *(float4*)&g_part[ks][b0 + i][c0] = v;
    }
}

// ---------------------------------------------------------------------------
// K4: per batch row: combine K-slices, divide by den, masked argmax (first-
// index tie rule), per-label sums, write one_hot(pred) * label_sums.
// committed is int32 (bool inputs are materialized as int32).
// ---------------------------------------------------------------------------
__global__ void k_epilogue(const int* __restrict__ committed,
                           const int* __restrict__ labels,
                           float* __restrict__ out) {
    int b = blockIdx.x;
    int t = threadIdx.x;  // 256
    __shared__ float bins[NUM_CLASSES];
    __shared__ float sVal[256];
    __shared__ int sIdx[256];

    if (t < NUM_CLASSES) bins[t] = 0.0f;
    __syncthreads();

    float best = -INFINITY;
    int bestIdx = 0;
    #pragma unroll
    for (int i = 0; i < 4; i++) {
        int c = t + i * 256;
        float num = 0.0f;
        #pragma unroll
        for (int s = 0; s < KSPLIT; s++) num += g_part[s][b][c];
        float v = num / g_den[c];
        bool com = (committed[c] != 0);
        float mv = com ? v : -INFINITY;
        if (mv > best) { best = mv; bestIdx = c; }  // ascending c -> first-index on tie
        if (com) atomicAdd(&bins[labels[c]], v);
    }
    sVal[t] = best;
    sIdx[t] = bestIdx;
    __syncthreads();
    for (int s = 128; s > 0; s >>= 1) {
        if (t < s) {
            float ov = sVal[t + s];
            int oi = sIdx[t + s];
            if (ov > sVal[t] || (ov == sVal[t] && oi < sIdx[t])) {
                sVal[t] = ov; sIdx[t] = oi;
            }
        }
        __syncthreads();
    }
    if (t < NUM_CLASSES) {
        int pl = labels[sIdx[0]];
        out[b * NUM_CLASSES + t] = (t == pl) ? bins[t] : 0.0f;
    }
}

// ---------------------------------------------------------------------------
extern "C" void kernel_launch(void* const* d_in, const int* in_sizes, int n_in,
                              void* d_out, int out_size) {
    const float* x = (const float*)d_in[0];
    const float* T = (const float*)d_in[1];
    const int* committed = (const int*)d_in[2];
    const int* labels = (const int*)d_in[3];
    const int* counts = (const int*)d_in[4];
    float* out = (float*)d_out;

    k_minmax_partial<<<B, 128>>>(x);
    k_prep<<<C + B, 256>>>(x, T, counts);
    dim3 g3(C / BN, B / BM, KSPLIT);
    k_choice<<<g3, 256>>>(T);
    k_epilogue<<<B, 256>>>(committed, labels, out);
}